// round 15
// baseline (speedup 1.0000x reference)
#include <cuda_runtime.h>
#include <cuda_bf16.h>
#include <math.h>
#include <cstdint>

// Problem constants (fixed by reference setup_inputs)
#define BSZ   4096
#define D0    2048
#define D1    128
#define NTOT  8192
#define TM    128
#define NT    (NTOT / TM)            // 64
#define NTILES_TRI (NT * (NT + 1) / 2)  // 2080
#define PERSIST_GRID 296             // 2 CTAs/SM x 148 SMs
// bf16 screen threshold vs exact threshold (margin covers bf16 dot error ~ +-6).
#define SCREEN_T 145.0f
#define EXACT_T  130.0f

#define QCAP  1024
#define BLOB  32768                   // one 128-row x 256B swizzled tile blob

// dynamic smem layout (bytes)
#define SM_A     0
#define SM_B     32768                // TWO B buffers (2 x 32KB)
#define SM_SQB   98304                // 2 buffers x 512B
#define SM_SQA   99328                // 2 buffers x 512B
#define SM_WRED  100352               // 8 floats
#define SM_MINB  100384               // 2 floats
#define SM_MBAR  100392               // 2 x 8B mbarriers
#define SM_QUEUE 100408
#define SM_QCNT  (SM_QUEUE + QCAP * 4)   // 104504
#define SM_TOTAL (SM_QCNT + 32)          // 104536

// ---- scratch (allocation-free rule: __device__ globals; zero-initialized at
// load, and reset by k_tile's last CTA at the end of every run) ----
__device__ float  g_sq0[NTOT];
__device__ float  g_sq1[NTOT];
__device__ float  g_colsum[D0];
__device__ double g_sum_sq0;
__device__ double g_acc;
__device__ float  g_inv_bw[5];
__device__ unsigned g_done_f0;
__device__ unsigned g_done_tile;
// bf16 copy of feature1, stored as 64 blobs of 128 rows x 256B, chunk-swizzled
__device__ __align__(128) __nv_bfloat16 g_x1[(size_t)NTOT * D1];

__device__ __forceinline__ uint32_t smem_u32(const void* p) {
    uint32_t a;
    asm("{ .reg .u64 t; cvta.to.shared.u64 t, %1; cvt.u32.u64 %0, t; }"
        : "=r"(a) : "l"(p));
    return a;
}

__device__ __forceinline__ void bulk_ld(uint32_t dst, const void* src,
                                        uint32_t bytes, uint32_t mbar) {
    asm volatile(
        "{\n\t.reg .u64 g;\n\tcvta.to.global.u64 g, %1;\n\t"
        "cp.async.bulk.shared::cluster.global.mbarrier::complete_tx::bytes "
        "[%0], [g], %2, [%3];\n\t}"
        :: "r"(dst), "l"(src), "r"(bytes), "r"(mbar) : "memory");
}

__device__ __forceinline__ void mbar_wait(uint32_t mbar, uint32_t parity) {
    asm volatile(
        "{\n\t.reg .pred P;\n\t"
        "WL_%=:\n\t"
        "mbarrier.try_wait.parity.acquire.cta.shared::cta.b64 P, [%0], %1, 0x989680;\n\t"
        "@P bra.uni WD_%=;\n\t"
        "bra.uni WL_%=;\n\t"
        "WD_%=:\n\t}"
        :: "r"(mbar), "r"(parity) : "memory");
}

// Cold path: exact scalar recompute (queue overflow only; keeps hot regs lean)
__device__ __noinline__ float pair_exact_scalar(
    int aa, int bb,
    const float* __restrict__ src0, const float* __restrict__ tar0,
    const float* __restrict__ src1, const float* __restrict__ tar1)
{
    const float* ra1 = (aa < BSZ) ? (src1 + (size_t)aa * D1)
                                  : (tar1 + (size_t)(aa - BSZ) * D1);
    const float* rb1 = (bb < BSZ) ? (src1 + (size_t)bb * D1)
                                  : (tar1 + (size_t)(bb - BSZ) * D1);
    float dp1 = 0.0f;
    for (int dd = 0; dd < D1; dd += 4) {
        float4 x = *(const float4*)(ra1 + dd);
        float4 y = *(const float4*)(rb1 + dd);
        dp1 += x.x * y.x + x.y * y.y + x.z * y.z + x.w * y.w;
    }
    float l21 = g_sq1[aa] + g_sq1[bb] - 2.0f * dp1;
    if (l21 >= EXACT_T) return 0.0f;
    const float* ra0 = (aa < BSZ) ? (src0 + (size_t)aa * D0)
                                  : (tar0 + (size_t)(aa - BSZ) * D0);
    const float* rb0 = (bb < BSZ) ? (src0 + (size_t)bb * D0)
                                  : (tar0 + (size_t)(bb - BSZ) * D0);
    float dp0 = 0.0f;
    for (int dd = 0; dd < D0; dd += 4) {
        float4 x = *(const float4*)(ra0 + dd);
        float4 y = *(const float4*)(rb0 + dd);
        dp0 += x.x * y.x + x.y * y.y + x.z * y.z + x.w * y.w;
    }
    float l20 = g_sq0[aa] + g_sq0[bb] - 2.0f * dp0;
    float k0v = 0.0f;
#pragma unroll
    for (int q = 0; q < 5; q++) k0v += expf(-l20 * g_inv_bw[q]);
    return k0v * expf(-l21 * (1.0f / 1.68f));
}

// ---------------------------------------------------------------------------
// K1: merged prologue. Blocks 0-511: feature-0 pass (row sq0 + col sums +
// total sq; last f0 block computes bandwidth constants). Blocks 512-767:
// feature-1 bf16 convert (swizzled blobs) + per-row sq1. The two roles touch
// disjoint state; accumulators were reset by the previous run's k_tile.
// ---------------------------------------------------------------------------
__global__ __launch_bounds__(256) void k_prep(
    const float* __restrict__ src0, const float* __restrict__ tar0,
    const float* __restrict__ src1, const float* __restrict__ tar1)
{
    int bid = blockIdx.x;
    int t = threadIdx.x;
    int w = t >> 5, l = t & 31;

    if (bid >= 512) {
        // ---- pre role: convert feature1, compute sq1 ----
        char* gx = (char*)g_x1;
        int base = (bid - 512) * 32 + w * 4;
#pragma unroll
        for (int rr4 = 0; rr4 < 4; rr4++) {
            int n = base + rr4;
            const float* r1 = (n < BSZ) ? (src1 + (size_t)n * D1)
                                        : (tar1 + (size_t)(n - BSZ) * D1);
            float4 v = ((const float4*)r1)[l];
            __nv_bfloat162 lo = __floats2bfloat162_rn(v.x, v.y);
            __nv_bfloat162 hi = __floats2bfloat162_rn(v.z, v.w);
            uint2 pk;
            pk.x = *(uint32_t*)&lo;
            pk.y = *(uint32_t*)&hi;
            int rr = n & 127;
            int c  = l >> 1;
            size_t off = (size_t)(n >> 7) * BLOB + (size_t)rr * 256
                       + (size_t)((c ^ (rr & 7)) << 4) + (size_t)(l & 1) * 8;
            *(uint2*)(gx + off) = pk;
            float s = v.x * v.x + v.y * v.y + v.z * v.z + v.w * v.w;
#pragma unroll
            for (int off2 = 16; off2; off2 >>= 1)
                s += __shfl_xor_sync(0xffffffffu, s, off2);
            if (l == 0) g_sq1[n] = s;
        }
        return;
    }

    // ---- f0 role: row sq0 + col sums + total sq over feature0 ----
    int d0 = (bid & 7) * 256;
    int nbase = (bid >> 3) * 128 + w * 16;
    float colacc[8] = {};
    double wsum = 0.0;
#pragma unroll 2
    for (int rr = 0; rr < 16; rr++) {
        int n = nbase + rr;
        const float* p = (n < BSZ) ? (src0 + (size_t)n * D0)
                                   : (tar0 + (size_t)(n - BSZ) * D0);
        float sq = 0.0f;
#pragma unroll
        for (int j = 0; j < 8; j++) {
            float v = p[d0 + l + j * 32];
            sq += v * v;
            colacc[j] += v;
        }
#pragma unroll
        for (int off = 16; off; off >>= 1)
            sq += __shfl_xor_sync(0xffffffffu, sq, off);
        if (l == 0) { atomicAdd(&g_sq0[n], sq); wsum += (double)sq; }
    }
    if (l == 0) atomicAdd(&g_sum_sq0, wsum);
#pragma unroll
    for (int j = 0; j < 8; j++)
        atomicAdd(&g_colsum[d0 + l + j * 32], colacc[j]);

    // --- last f0 CTA: bandwidth finalize ---
    __shared__ bool isLast;
    __syncthreads();
    if (t == 0) {
        __threadfence();
        unsigned o = atomicAdd(&g_done_f0, 1u);
        isLast = (o == 512u - 1u);
    }
    __syncthreads();
    if (isLast) {
        double s = 0.0;
#pragma unroll
        for (int j = 0; j < 8; j++) {
            double c = (double)g_colsum[t + j * 256];
            s += c * c;
        }
#pragma unroll
        for (int off = 16; off; off >>= 1)
            s += __shfl_xor_sync(0xffffffffu, s, off);
        __shared__ double red[8];
        if ((t & 31) == 0) red[t >> 5] = s;
        __syncthreads();
        if (t == 0) {
            double tot = 0.0;
#pragma unroll
            for (int i = 0; i < 8; i++) tot += red[i];
            double sum_l2 = 2.0 * (double)NTOT * g_sum_sq0 - 2.0 * tot;
            double bw = sum_l2 / ((double)NTOT * (double)NTOT - (double)NTOT) / 4.0;
#pragma unroll
            for (int i = 0; i < 5; i++)
                g_inv_bw[i] = (float)(1.0 / (bw * (double)(1 << i)));
        }
    }
}

__device__ __forceinline__ void unrank_tri(int idx, int& by, int& bx) {
    int r = (int)((2.0 * NT + 1.0
                   - sqrt((2.0 * NT + 1.0) * (2.0 * NT + 1.0) - 8.0 * idx)) * 0.5);
    if (r < 0) r = 0;
    while (r * NT - r * (r - 1) / 2 > idx) r--;
    while ((r + 1) * NT - (r + 1) * r / 2 <= idx) r++;
    by = r;
    bx = r + (idx - (r * NT - r * (r - 1) / 2));
}

// ---------------------------------------------------------------------------
// K4: persistent bf16 HMMA screening GEMM. Contiguous row-major tile ranges
// per CTA (A blob reused across a row run). Double-buffered B + sq strips,
// all fills via cp.async.bulk on per-buffer mbarriers. Fast-path screen +
// queue exact epilogue. Last CTA writes scalar AND resets accumulators for
// the next replay.
// ---------------------------------------------------------------------------
__global__ __launch_bounds__(256, 2) void k_tile(
    const float* __restrict__ src0, const float* __restrict__ tar0,
    const float* __restrict__ src1, const float* __restrict__ tar1,
    float* __restrict__ out)
{
    extern __shared__ __align__(128) char dsm[];
    float*    sqbbuf = (float*)(dsm + SM_SQB);      // [2][128]
    float*    sqabuf = (float*)(dsm + SM_SQA);      // [2][128]
    float*    wred   = (float*)(dsm + SM_WRED);
    float*    minb   = (float*)(dsm + SM_MINB);     // [2]
    uint32_t* queue  = (uint32_t*)(dsm + SM_QUEUE);
    uint32_t* qcount = (uint32_t*)(dsm + SM_QCNT);

    int tid = threadIdx.x;
    int wid = tid >> 5, lane = tid & 31;
    int wy = wid >> 1, wx = wid & 1;    // 4x2 warp grid, warp tile 32x64

    uint32_t sAb   = smem_u32(dsm + SM_A);
    uint32_t sBb   = smem_u32(dsm + SM_B);          // base of buffer 0
    uint32_t sSqB  = smem_u32(sqbbuf);
    uint32_t sSqA  = smem_u32(sqabuf);
    uint32_t mbar0 = smem_u32(dsm + SM_MBAR);       // mbar0, mbar0+8

    uint32_t rA = (uint32_t)(wy * 32 + (lane & 15));
    uint32_t rB = (uint32_t)(wx * 64 + ((lane >> 3) & 1) * 8 + (lane & 7));
    uint32_t preA  = sAb + rA * 256;
    uint32_t preB0 = sBb + rB * 256;
    uint32_t lxor = (uint32_t)(lane & 7);
    uint32_t kbit = (uint32_t)(lane >> 4);

    const char* gx = (const char*)g_x1;

    if (tid == 0) {
        *qcount = 0;
        asm volatile("mbarrier.init.shared.b64 [%0], %1;" :: "r"(mbar0), "r"(1u) : "memory");
        asm volatile("mbarrier.init.shared.b64 [%0], %1;" :: "r"(mbar0 + 8), "r"(1u) : "memory");
    }
    __syncthreads();

    // contiguous tile range for this CTA
    int cstart = (int)(((long long)blockIdx.x * NTILES_TRI) / PERSIST_GRID);
    int cend   = (int)(((long long)(blockIdx.x + 1) * NTILES_TRI) / PERSIST_GRID);
    int by, bx;
    unrank_tri(cstart, by, bx);

    // prologue: A + B(0) + sq strips into buffer 0 (all bulk, one mbarrier)
    if (tid == 0) {
        asm volatile("mbarrier.arrive.expect_tx.shared.b64 _, [%0], %1;"
                     :: "r"(mbar0), "r"(2u * BLOB + 1024u) : "memory");
        bulk_ld(sAb, gx + (size_t)by * BLOB, BLOB, mbar0);
        bulk_ld(sBb, gx + (size_t)bx * BLOB, BLOB, mbar0);
        bulk_ld(sSqB, g_sq1 + bx * TM, 512, mbar0);
        bulk_ld(sSqA, g_sq1 + by * TM, 512, mbar0);
    }

    int it = 0;
    for (int idx = cstart; idx < cend; idx++, it++) {
        int buf = it & 1;
        int arow0 = by * TM, brow0 = bx * TM;
        float* sqb = sqbbuf + buf * 128;
        float* sqa = sqabuf + buf * 128;
        uint32_t mbar = mbar0 + (uint32_t)buf * 8;
        uint32_t preB = preB0 + (uint32_t)buf * BLOB;

        mbar_wait(mbar, (uint32_t)((it >> 1) & 1));
        __syncthreads();

        // --- pre-MMA: issue B(i+1) + sq strips into buf^1 (overlap MMA) ---
        int nby = by, nbx = bx;
        bool have_next = (idx + 1 < cend);
        bool rowchg = false;
        if (have_next) {
            nbx = bx + 1;
            if (nbx == NT) { nby = by + 1; nbx = nby; rowchg = true; }
            if (tid == 0) {
                asm volatile("fence.proxy.async.shared::cta;" ::: "memory");
                uint32_t nmbar = mbar0 + (uint32_t)(buf ^ 1) * 8;
                uint32_t tx = (rowchg ? 2u * BLOB : BLOB) + 1024u;
                asm volatile("mbarrier.arrive.expect_tx.shared.b64 _, [%0], %1;"
                             :: "r"(nmbar), "r"(tx) : "memory");
                bulk_ld(sBb + (uint32_t)(buf ^ 1) * BLOB,
                        gx + (size_t)nbx * BLOB, BLOB, nmbar);
                bulk_ld(sSqB + (uint32_t)(buf ^ 1) * 512, g_sq1 + nbx * TM, 512, nmbar);
                bulk_ld(sSqA + (uint32_t)(buf ^ 1) * 512, g_sq1 + nby * TM, 512, nmbar);
            }
        }

        // per-tile min of sqb (warp 0) -- published by the post-MMA sync
        if (wid == 0) {
            float m = fminf(fminf(sqb[lane], sqb[lane + 32]),
                            fminf(sqb[lane + 64], sqb[lane + 96]));
#pragma unroll
            for (int off = 16; off; off >>= 1)
                m = fminf(m, __shfl_xor_sync(0xffffffffu, m, off));
            if (lane == 0) minb[buf] = m;
        }

        // --- MMA mainloop: 8 K16 steps ---
        float acc[2][8][4];
#pragma unroll
        for (int mt = 0; mt < 2; mt++)
#pragma unroll
            for (int nt = 0; nt < 8; nt++)
#pragma unroll
                for (int v = 0; v < 4; v++) acc[mt][nt][v] = 0.0f;

#pragma unroll
        for (int ks = 0; ks < 8; ks++) {
            uint32_t sw = (((uint32_t)(2 * ks) + kbit) ^ lxor) << 4;
            uint32_t a[2][4];
#pragma unroll
            for (int mt = 0; mt < 2; mt++) {
                asm volatile(
                    "ldmatrix.sync.aligned.m8n8.x4.shared.b16 {%0,%1,%2,%3}, [%4];"
                    : "=r"(a[mt][0]), "=r"(a[mt][1]), "=r"(a[mt][2]), "=r"(a[mt][3])
                    : "r"(preA + (uint32_t)(mt * 4096) + sw));
            }
            uint32_t b[4][4];
#pragma unroll
            for (int np = 0; np < 4; np++) {
                asm volatile(
                    "ldmatrix.sync.aligned.m8n8.x4.shared.b16 {%0,%1,%2,%3}, [%4];"
                    : "=r"(b[np][0]), "=r"(b[np][1]), "=r"(b[np][2]), "=r"(b[np][3])
                    : "r"(preB + (uint32_t)(np * 4096) + sw));
            }
#pragma unroll
            for (int mt = 0; mt < 2; mt++)
#pragma unroll
                for (int nt = 0; nt < 8; nt++) {
                    uint32_t b0 = b[nt >> 1][(nt & 1)];
                    uint32_t b1 = b[nt >> 1][(nt & 1) + 2];
                    float* c = acc[mt][nt];
                    asm volatile(
                        "mma.sync.aligned.m16n8k16.row.col.f32.bf16.bf16.f32 "
                        "{%0,%1,%2,%3}, {%4,%5,%6,%7}, {%8,%9}, {%0,%1,%2,%3};"
                        : "+f"(c[0]), "+f"(c[1]), "+f"(c[2]), "+f"(c[3])
                        : "r"(a[mt][0]), "r"(a[mt][1]), "r"(a[mt][2]), "r"(a[mt][3]),
                          "r"(b0), "r"(b1));
                }
        }
        __syncthreads();   // A/B consumed; minb[buf] visible

        // --- post-MMA: A reload on row change (A buffer now free) ---
        if (have_next && rowchg && tid == 0) {
            asm volatile("fence.proxy.async.shared::cta;" ::: "memory");
            bulk_ld(sAb, gx + (size_t)nby * BLOB, BLOB,
                    mbar0 + (uint32_t)(buf ^ 1) * 8);
        }

        // --- screen with fast-path skip ---
        float sqa0 = sqa[wy * 32 + (lane >> 2)];
        float sqa1 = sqa[wy * 32 + (lane >> 2) + 8];
        float sqa2 = sqa[wy * 32 + 16 + (lane >> 2)];
        float sqa3 = sqa[wy * 32 + 16 + (lane >> 2) + 8];

        float local = 0.0f;
        {
            float maxacc = acc[0][0][0];
#pragma unroll
            for (int mt = 0; mt < 2; mt++)
#pragma unroll
                for (int nt = 0; nt < 8; nt++)
#pragma unroll
                    for (int v = 0; v < 4; v++)
                        maxacc = fmaxf(maxacc, acc[mt][nt][v]);
            float minsqa = fminf(fminf(sqa0, sqa1), fminf(sqa2, sqa3));
            bool skip = (minsqa + minb[buf] - 2.0f * maxacc) >= SCREEN_T;
            if (!skip) {
#pragma unroll
                for (int mt = 0; mt < 2; mt++) {
#pragma unroll
                    for (int nt = 0; nt < 8; nt++) {
#pragma unroll
                        for (int v = 0; v < 4; v++) {
                            int arow = wy * 32 + mt * 16 + (lane >> 2) + 8 * (v >> 1);
                            int col  = wx * 64 + nt * 8 + (lane & 3) * 2 + (v & 1);
                            float sqav = mt ? ((v >> 1) ? sqa3 : sqa2)
                                            : ((v >> 1) ? sqa1 : sqa0);
                            float l2s = sqav + sqb[col] - 2.0f * acc[mt][nt][v];
                            if (l2s < SCREEN_T) {
                                int aa = arow0 + arow;
                                int bb = brow0 + col;
                                if (aa == bb) {
                                    local += 5.0f;   // k1=1, k0=5 at l2=0
                                } else {
                                    uint32_t pos = atomicAdd(qcount, 1u);
                                    if (pos < QCAP)
                                        queue[pos] = ((uint32_t)arow << 8) | (uint32_t)col;
                                    else
                                        local += pair_exact_scalar(aa, bb, src0, tar0,
                                                                   src1, tar1);
                                }
                            }
                        }
                    }
                }
            }
        }
        __syncthreads();

        // --- queue: warp-cooperative exact recompute ---
        uint32_t cnt = *qcount;
        if (cnt > QCAP) cnt = QCAP;
        float wq = 0.0f;
        for (uint32_t q = (uint32_t)wid; q < cnt; q += 8) {
            uint32_t e = queue[q];
            int aa = arow0 + (int)(e >> 8);
            int bb = brow0 + (int)(e & 255u);
            const float* ra1 = (aa < BSZ) ? (src1 + (size_t)aa * D1)
                                          : (tar1 + (size_t)(aa - BSZ) * D1);
            const float* rb1 = (bb < BSZ) ? (src1 + (size_t)bb * D1)
                                          : (tar1 + (size_t)(bb - BSZ) * D1);
            float4 x = ((const float4*)ra1)[lane];
            float4 y = ((const float4*)rb1)[lane];
            float dp1 = x.x * y.x + x.y * y.y + x.z * y.z + x.w * y.w;
#pragma unroll
            for (int off = 16; off; off >>= 1)
                dp1 += __shfl_xor_sync(0xffffffffu, dp1, off);
            float l21 = g_sq1[aa] + g_sq1[bb] - 2.0f * dp1;
            if (l21 < EXACT_T) {
                const float* ra0 = (aa < BSZ) ? (src0 + (size_t)aa * D0)
                                              : (tar0 + (size_t)(aa - BSZ) * D0);
                const float* rb0 = (bb < BSZ) ? (src0 + (size_t)bb * D0)
                                              : (tar0 + (size_t)(bb - BSZ) * D0);
                float dp0 = 0.0f;
#pragma unroll
                for (int itn = 0; itn < 16; itn++) {
                    float4 xx = ((const float4*)ra0)[lane + itn * 32];
                    float4 yy = ((const float4*)rb0)[lane + itn * 32];
                    dp0 += xx.x * yy.x + xx.y * yy.y + xx.z * yy.z + xx.w * yy.w;
                }
#pragma unroll
                for (int off = 16; off; off >>= 1)
                    dp0 += __shfl_xor_sync(0xffffffffu, dp0, off);
                float l20 = g_sq0[aa] + g_sq0[bb] - 2.0f * dp0;
                float k0v = 0.0f;
#pragma unroll
                for (int qq = 0; qq < 5; qq++)
                    k0v += expf(-l20 * g_inv_bw[qq]);
                if (lane == 0) wq += k0v * expf(-l21 * (1.0f / 1.68f));
            }
        }

        // --- reduce + signed/weighted accumulate ---
#pragma unroll
        for (int off = 16; off; off >>= 1)
            local += __shfl_xor_sync(0xffffffffu, local, off);
        if (lane == 0) wred[wid] = local + wq;
        __syncthreads();
        if (tid == 0) {
            float rsum = 0.0f;
#pragma unroll
            for (int i = 0; i < 8; i++) rsum += wred[i];
            if (rsum != 0.0f) {
                float w   = (bx == by) ? 1.0f : 2.0f;
                float sgn = ((by < NT / 2) == (bx < NT / 2)) ? 1.0f : -1.0f;
                atomicAdd(&g_acc, (double)(rsum * w * sgn));
            }
            *qcount = 0;      // ordered before next screen by the syncs above it
        }
        by = nby; bx = nbx;
    }

    // --- last persistent CTA: write scalar + reset state for next replay ---
    __shared__ bool amLast;
    __syncthreads();
    if (tid == 0) {
        __threadfence();
        unsigned o = atomicAdd(&g_done_tile, 1u);
        amLast = (o == PERSIST_GRID - 1);
    }
    __syncthreads();
    if (amLast) {
        if (tid == 0) {
            out[0] = (float)(g_acc / ((double)BSZ * (double)BSZ));
            g_acc = 0.0;
            g_sum_sq0 = 0.0;
            g_done_f0 = 0u;
            g_done_tile = 0u;
        }
        for (int i = tid; i < NTOT; i += 256) g_sq0[i] = 0.0f;
        for (int i = tid; i < D0; i += 256) g_colsum[i] = 0.0f;
    }
}

extern "C" void kernel_launch(void* const* d_in, const int* in_sizes, int n_in,
                              void* d_out, int out_size)
{
    const float* src0 = (const float*)d_in[0];
    const float* src1 = (const float*)d_in[1];
    const float* tar0 = (const float*)d_in[2];
    const float* tar1 = (const float*)d_in[3];
    float* out = (float*)d_out;

    cudaFuncSetAttribute(k_tile, cudaFuncAttributeMaxDynamicSharedMemorySize, SM_TOTAL);

    k_prep<<<768, 256>>>(src0, tar0, src1, tar1);
    k_tile<<<PERSIST_GRID, 256, SM_TOTAL>>>(src0, tar0, src1, tar1, out);
}